// round 14
// baseline (speedup 1.0000x reference)
#include <cuda_runtime.h>
#include <math.h>
#include <stdint.h>

#define B_      2
#define SEQ     1024
#define DIM_    1024
#define HEADS_  16
#define DH_     64
#define MLP_    4096
#define ROWS    (B_*SEQ)          // 2048
#define SCALE_  0.125f            // 64^-0.5
#define DEPTH_  2

// ---------------- scratch (device globals: allocation-guard-safe) -------------
__device__ float g_h   [ROWS*DIM_];
__device__ float g_qkv [ROWS*3*DIM_];
__device__ float g_q2  [ROWS*DIM_];
__device__ float g_k2  [ROWS*DIM_];
__device__ float g_v2  [ROWS*DIM_];
__device__ float g_o   [ROWS*DIM_];
__device__ float g_mlp [ROWS*MLP_];
__device__ float g_ctx [ROWS*DIM_];   // pre-rounded ctx

// ---------------- helpers ------------------------------------------------------
__device__ __forceinline__ uint32_t f2tf(float f) {
    uint32_t r;
    asm("cvt.rna.tf32.f32 %0, %1;" : "=r"(r) : "f"(f));
    return r;
}
__device__ __forceinline__ float tfr(float f) { return __uint_as_float(f2tf(f)); }
__device__ __forceinline__ uint32_t f2b(float f) { return __float_as_uint(f); }

__device__ __forceinline__ void mma8(float* c, const uint32_t* a, const uint32_t* b) {
    asm volatile(
        "mma.sync.aligned.m16n8k8.row.col.f32.tf32.tf32.f32 "
        "{%0,%1,%2,%3}, {%4,%5,%6,%7}, {%8,%9}, {%0,%1,%2,%3};"
        : "+f"(c[0]), "+f"(c[1]), "+f"(c[2]), "+f"(c[3])
        : "r"(a[0]), "r"(a[1]), "r"(a[2]), "r"(a[3]),
          "r"(b[0]), "r"(b[1]));
}

// P-matrix fragment index (scalar 33-stride layout; write scatter conflict-free)
__device__ __forceinline__ int aidx(int row, int k) {
    const int reg = ((k & 7) >> 2) * 2 + ((row & 15) >> 3);
    return (((reg * 8 + (k >> 3)) * 4 + (row >> 4)) * 33) + (row & 7) * 4 + (k & 3);
}

// ---------------- pre-round pass (ctx only) ------------------------------------
__global__ __launch_bounds__(256) void round_k(
    const float4* __restrict__ in, float4* __restrict__ out, int n4)
{
    const int stride = gridDim.x * blockDim.x;
    for (int i = blockIdx.x*blockDim.x + threadIdx.x; i < n4; i += stride) {
        float4 v = in[i];
        v.x = tfr(v.x); v.y = tfr(v.y); v.z = tfr(v.z); v.w = tfr(v.w);
        out[i] = v;
    }
}

// ---------------- layernorm: one block per row, tf32-rounded output ----------
__global__ __launch_bounds__(256) void layernorm_k(
    const float* __restrict__ x, const float* __restrict__ g,
    const float* __restrict__ b, float* __restrict__ out)
{
    __shared__ float red[18];
    const int row = blockIdx.x;
    const int t   = threadIdx.x;
    const float4 v = ((const float4*)(x + (size_t)row*DIM_))[t];
    float s  = v.x + v.y + v.z + v.w;
    float sq = v.x*v.x + v.y*v.y + v.z*v.z + v.w*v.w;
    #pragma unroll
    for (int o = 16; o > 0; o >>= 1) {
        s  += __shfl_down_sync(0xffffffffu, s,  o);
        sq += __shfl_down_sync(0xffffffffu, sq, o);
    }
    if ((t & 31) == 0) { red[t >> 5] = s; red[8 + (t >> 5)] = sq; }
    __syncthreads();
    if (t < 32) {
        float a = (t < 8) ? red[t]     : 0.f;
        float c = (t < 8) ? red[8 + t] : 0.f;
        #pragma unroll
        for (int o = 4; o > 0; o >>= 1) {
            a += __shfl_down_sync(0xffffffffu, a, o);
            c += __shfl_down_sync(0xffffffffu, c, o);
        }
        if (t == 0) { red[16] = a; red[17] = c; }
    }
    __syncthreads();
    const float mu   = red[16] * (1.f / DIM_);
    const float var  = red[17] * (1.f / DIM_) - mu * mu;
    const float rstd = rsqrtf(var + 1e-5f);
    const float4 gv = ((const float4*)g)[t];
    const float4 bv = ((const float4*)b)[t];
    float4 o4;
    o4.x = tfr((v.x - mu) * rstd * gv.x + bv.x);
    o4.y = tfr((v.y - mu) * rstd * gv.y + bv.y);
    o4.z = tfr((v.z - mu) * rstd * gv.z + bv.z);
    o4.w = tfr((v.w - mu) * rstd * gv.w + bv.w);
    ((float4*)(out + (size_t)row*DIM_))[t] = o4;
}

// ---------------- TF32 GEMM 128x128x32 (round-13 body, unchanged) -------------
__device__ __forceinline__ void gemm_body(
    const float* __restrict__ A, const float* __restrict__ B,
    const float* __restrict__ bias, const float* __restrict__ res,
    float* __restrict__ C, int M, int N, int K, int act,
    int bm, int bn)
{
    __shared__ __align__(16) uint32_t As[4224];
    __shared__ __align__(16) uint32_t Bs[4224];

    const int tid    = threadIdx.x;
    const int lane   = tid & 31;
    const int warp   = tid >> 5;
    const int warp_m = warp >> 2;
    const int warp_n = warp & 3;

    const int ar  = tid >> 3;
    const int aq  = tid & 7;
    const int bkr = tid >> 5;
    const int bq  = tid & 31;

    const float* Abase = A + (size_t)(bm*128)*K;
    const float* Bbase = B + (size_t)(bn*128);

    const int a_j  = aq >> 1;
    const int a_rk = 2*(aq & 1);

    float4 pa[4], pb[4];
    #pragma unroll
    for (int it = 0; it < 4; it++) {
        pa[it] = *(const float4*)(Abase + (size_t)(ar + it*32)*K + aq*4);
        pb[it] = *(const float4*)(Bbase + (size_t)(bkr + it*8)*N + bq*4);
    }

    float acc[4][4][4];
    #pragma unroll
    for (int mi = 0; mi < 4; mi++)
        #pragma unroll
        for (int ni = 0; ni < 4; ni++)
            #pragma unroll
            for (int r = 0; r < 4; r++) acc[mi][ni][r] = 0.f;

    const uint32_t* a_rd = As + lane*4;
    const uint32_t* b_rd = Bs + lane*2;

    for (int kt = 0; kt < K; kt += 32) {
        #pragma unroll
        for (int it = 0; it < 4; it++) {
            {
                const int row = ar + it*32;
                const int i   = row >> 4;
                uint32_t* d = &As[(i*4 + a_j)*132 + (row & 7)*16
                                  + a_rk + ((row & 15) >> 3)];
                d[0]  = f2b(pa[it].x);
                d[4]  = f2b(pa[it].y);
                d[8]  = f2b(pa[it].z);
                d[12] = f2b(pa[it].w);
            }
            {
                const int kb = bkr + it*8;
                uint32_t* e = &Bs[((kb >> 3)*16 + (bq >> 1))*66
                                  + (16*(bq & 1) + (kb & 3))*2 + ((kb & 7) >> 2)];
                e[0]  = f2tf(pb[it].x);
                e[8]  = f2tf(pb[it].y);
                e[16] = f2tf(pb[it].z);
                e[24] = f2tf(pb[it].w);
            }
        }
        __syncthreads();

        if (kt + 32 < K) {
            #pragma unroll
            for (int it = 0; it < 4; it++) {
                pa[it] = *(const float4*)(Abase + (size_t)(ar + it*32)*K + (kt + 32) + aq*4);
                pb[it] = *(const float4*)(Bbase + (size_t)(bkr + it*8 + kt + 32)*N + bq*4);
            }
        }

        #pragma unroll
        for (int j = 0; j < 4; j++) {
            uint4 af[4];
            #pragma unroll
            for (int mi = 0; mi < 4; mi++)
                af[mi] = *(const uint4*)(a_rd + ((warp_m*4 + mi)*4 + j)*132);
            uint2 bf[4];
            #pragma unroll
            for (int ni = 0; ni < 4; ni++)
                bf[ni] = *(const uint2*)(b_rd + (j*16 + warp_n*4 + ni)*66);
            #pragma unroll
            for (int mi = 0; mi < 4; mi++)
                #pragma unroll
                for (int ni = 0; ni < 4; ni++)
                    mma8(acc[mi][ni], (const uint32_t*)&af[mi],
                         (const uint32_t*)&bf[ni]);
        }
        __syncthreads();
    }

    const int r0 = bm*128 + warp_m*64 + (lane >> 2);
    const int c0 = bn*128 + warp_n*32 + 2*(lane & 3);
    #pragma unroll
    for (int mi = 0; mi < 4; mi++) {
        #pragma unroll
        for (int ni = 0; ni < 4; ni++) {
            const int c = c0 + ni*8;
            float2 bv = make_float2(0.f, 0.f);
            if (bias) bv = *(const float2*)&bias[c];
            #pragma unroll
            for (int half = 0; half < 2; half++) {
                const int r = r0 + mi*16 + half*8;
                const size_t idx = (size_t)r * N + c;
                float vx = acc[mi][ni][half*2 + 0] + bv.x;
                float vy = acc[mi][ni][half*2 + 1] + bv.y;
                if (act & 1) { vx = vx * normcdff(vx); vy = vy * normcdff(vy); }
                if (act & 2) { vx = tfr(vx); vy = tfr(vy); }
                if (res) { vx += res[idx]; vy += res[idx + 1]; }
                *(float2*)&C[idx] = make_float2(vx, vy);
            }
        }
    }
}

__global__ __launch_bounds__(256) void tcgemm_k(
    const float* __restrict__ A, const float* __restrict__ B,
    const float* __restrict__ bias, const float* __restrict__ res,
    float* __restrict__ C, int M, int N, int K, int act)
{
    gemm_body(A, B, bias, res, C, M, N, K, act, blockIdx.y, blockIdx.x);
}

__global__ __launch_bounds__(256) void tcgemm3_k(
    const float* __restrict__ A0, const float* __restrict__ A1,
    const float* __restrict__ A2,
    const float* __restrict__ B0, const float* __restrict__ B1,
    const float* __restrict__ B2,
    float* __restrict__ C0, float* __restrict__ C1, float* __restrict__ C2)
{
    const int z = blockIdx.z;
    const float* A = (z == 0) ? A0 : (z == 1) ? A1 : A2;
    const float* B = (z == 0) ? B0 : (z == 1) ? B1 : B2;
    float*       C = (z == 0) ? C0 : (z == 1) ? C1 : C2;
    gemm_body(A, B, nullptr, nullptr, C, ROWS, DIM_, DIM_, 2,
              blockIdx.y, blockIdx.x);
}

// ---------------- fused flash attention, vector-frag Q/K/V --------------------
// Qs: A-frag vector (M=64,K=64): frag(i,j)=i*8+j, word=frag*132+lane*4+r
// Ks: B-frag vector (N=64 kv,K=64 dh): frag(j,nt)=j*8+nt, word=frag*66+lane*2+r
//     (aliased by Ps in the scalar 33-stride layout after S is consumed)
// Vs: B-frag vector (N=64 dh,K=64 kv): same shape as Ks
__global__ __launch_bounds__(256) void flash_k(
    const float* __restrict__ Q, int ldq,
    const float* __restrict__ Kp, int ldk,
    const float* __restrict__ V, int ldv,
    float* __restrict__ O)
{
    extern __shared__ uint32_t fsm[];
    uint32_t* Qs = fsm;
    uint32_t* Ks = fsm + 4224;      // also Ps
    uint32_t* Vs = fsm + 8448;
    __shared__ float row_m[64], row_l[64];
    __shared__ float pmax[2][64], psum[2][64];

    const int bh = blockIdx.y, b = bh >> 4, h = bh & 15;
    const int q0 = blockIdx.x * 64;
    const int tid = threadIdx.x, lane = tid & 31, warp = tid >> 5;
    const int wm = warp >> 1, wn = warp & 1;

    // ---- Q fill into vector A-frag layout (pre-rounded inputs, raw bits) ----
    {
        const float* qb = Q + (size_t)(b*SEQ + q0) * ldq + h*DH_;
        const int row0 = tid >> 3;      // 0..31
        const int qq0  = tid & 7;       // 0..7
        #pragma unroll
        for (int it = 0; it < 4; it++) {
            const int row = row0 + 32*(it & 1);
            const int q   = qq0  + 8*(it >> 1);
            const float4 v = *(const float4*)(qb + (size_t)row*ldq + q*4);
            uint32_t* d = &Qs[((row >> 4)*8 + (q >> 1))*132 + (row & 7)*16
                              + 2*(q & 1) + ((row & 8) >> 3)];
            d[0]  = f2b(v.x * SCALE_);
            d[4]  = f2b(v.y * SCALE_);
            d[8]  = f2b(v.z * SCALE_);
            d[12] = f2b(v.w * SCALE_);
        }
    }
    if (tid < 64) { row_m[tid] = -1e30f; row_l[tid] = 0.f; }

    float o[4][4];
    #pragma unroll
    for (int ni = 0; ni < 4; ni++)
        #pragma unroll
        for (int c = 0; c < 4; c++) o[ni][c] = 0.f;

    const int r0 = wm*16 + (lane >> 2);
    const int r1 = r0 + 8;

    for (int kt = 0; kt < SEQ; kt += 64) {
        __syncthreads();
        // ---- K/V fill into vector B-frag layouts ----
        {
            const float* kb = Kp + (size_t)(b*SEQ + kt) * ldk + h*DH_;
            const int kn0 = tid >> 3;       // kv row 0..31
            const int kq0 = tid & 7;        // dh quad 0..7
            #pragma unroll
            for (int it = 0; it < 4; it++) {
                const int n = kn0 + 32*(it & 1);
                const int q = kq0 + 8*(it >> 1);
                const float4 kv4 = *(const float4*)(kb + (size_t)n*ldk + q*4);
                uint32_t* e = &Ks[((q >> 1)*8 + (n >> 3))*66 + (n & 7)*8 + (q & 1)];
                e[0] = f2b(kv4.x); e[2] = f2b(kv4.y);
                e[4] = f2b(kv4.z); e[6] = f2b(kv4.w);
            }
            const float* vb = V + (size_t)(b*SEQ + kt) * ldv + h*DH_;
            const int vk = tid & 63;        // kv row 0..63
            const int vg = tid >> 6;        // 0..3
            #pragma unroll
            for (int it = 0; it < 4; it++) {
                const int nq = vg*4 + it;   // dh quad 0..15
                const float4 vv4 = *(const float4*)(vb + (size_t)vk*ldv + nq*4);
                uint32_t* f = &Vs[((vk >> 3)*8 + (nq >> 1))*66 + 32*(nq & 1)
                                  + (vk & 3)*2 + ((vk & 4) >> 2)];
                f[0]  = f2b(vv4.x);
                f[8]  = f2b(vv4.y);
                f[16] = f2b(vv4.z);
                f[24] = f2b(vv4.w);
            }
        }
        __syncthreads();

        // ---- S = Q K^T (vectorized fragment loads) ----
        float s[4][4];
        #pragma unroll
        for (int ni = 0; ni < 4; ni++)
            #pragma unroll
            for (int c = 0; c < 4; c++) s[ni][c] = 0.f;
        #pragma unroll
        for (int j = 0; j < 8; j++) {
            const uint4 af = *(const uint4*)(Qs + (wm*8 + j)*132 + lane*4);
            #pragma unroll
            for (int ni = 0; ni < 4; ni++) {
                const uint2 bf = *(const uint2*)(Ks + (j*8 + wn*4 + ni)*66 + lane*2);
                mma8(s[ni], (const uint32_t*)&af, (const uint32_t*)&bf);
            }
        }

        // ---- online softmax (unchanged) ----
        float mx0 = -1e30f, mx1 = -1e30f;
        #pragma unroll
        for (int ni = 0; ni < 4; ni++) {
            mx0 = fmaxf(mx0, fmaxf(s[ni][0], s[ni][1]));
            mx1 = fmaxf(mx1, fmaxf(s[ni][2], s[ni][3]));
        }
        mx0 = fmaxf(mx0, __shfl_xor_sync(0xffffffffu, mx0, 1));
        mx0 = fmaxf(mx0, __shfl_xor_sync(0xffffffffu, mx0, 2));
        mx1 = fmaxf(mx1, __shfl_xor_sync(0xffffffffu, mx1, 1));
        mx1 = fmaxf(mx1, __shfl_xor_sync(0xffffffffu, mx1, 2));
        if ((lane & 3) == 0) { pmax[wn][r0] = mx0; pmax[wn][r1] = mx1; }
        __syncthreads();

        const float mo0 = row_m[r0], mo1 = row_m[r1];
        const float mn0 = fmaxf(mo0, fmaxf(pmax[0][r0], pmax[1][r0]));
        const float mn1 = fmaxf(mo1, fmaxf(pmax[0][r1], pmax[1][r1]));
        const float al0 = __expf(mo0 - mn0);
        const float al1 = __expf(mo1 - mn1);

        float sum0 = 0.f, sum1 = 0.f;
        #pragma unroll
        for (int ni = 0; ni < 4; ni++) {
            const int cb = wn*32 + ni*8 + (lane & 3)*2;
            float p00 = __expf(s[ni][0] - mn0);
            float p01 = __expf(s[ni][1] - mn0);
            float p10 = __expf(s[ni][2] - mn1);
            float p11 = __expf(s[ni][3] - mn1);
            sum0 += p00 + p01;
            sum1 += p10 + p11;
            Ks[aidx(r0, cb    )] = f2tf(p00);   // Ps aliases Ks (scalar layout)
            Ks[aidx(r0, cb + 1)] = f2tf(p01);
            Ks[aidx(r1, cb    )] = f2tf(p10);
            Ks[aidx(r1, cb + 1)] = f2tf(p11);
        }
        sum0 += __shfl_xor_sync(0xffffffffu, sum0, 1);
        sum0 += __shfl_xor_sync(0xffffffffu, sum0, 2);
        sum1 += __shfl_xor_sync(0xffffffffu, sum1, 1);
        sum1 += __shfl_xor_sync(0xffffffffu, sum1, 2);
        if ((lane & 3) == 0) { psum[wn][r0] = sum0; psum[wn][r1] = sum1; }

        #pragma unroll
        for (int ni = 0; ni < 4; ni++) {
            o[ni][0] *= al0; o[ni][1] *= al0;
            o[ni][2] *= al1; o[ni][3] *= al1;
        }
        __syncthreads();

        if (wn == 0 && (lane & 3) == 0) {
            row_m[r0] = mn0; row_m[r1] = mn1;
            row_l[r0] = row_l[r0]*al0 + psum[0][r0] + psum[1][r0];
            row_l[r1] = row_l[r1]*al1 + psum[0][r1] + psum[1][r1];
        }

        // ---- O += P V (P scalar reads, V vector reads) ----
        #pragma unroll
        for (int j = 0; j < 8; j++) {
            uint32_t af[4];
            #pragma unroll
            for (int r = 0; r < 4; r++)
                af[r] = Ks[((r*8 + j)*4 + wm)*33 + lane];
            #pragma unroll
            for (int ni = 0; ni < 4; ni++) {
                const uint2 bf = *(const uint2*)(Vs + (j*8 + wn*4 + ni)*66 + lane*2);
                mma8(o[ni], af, (const uint32_t*)&bf);
            }
        }
    }
    __syncthreads();

    const float inv0 = 1.f / row_l[r0];
    const float inv1 = 1.f / row_l[r1];
    float* ob = O + (size_t)(b*SEQ + q0) * DIM_ + h*DH_;
    #pragma unroll
    for (int ni = 0; ni < 4; ni++) {
        const int c = wn*32 + ni*8 + (lane & 3)*2;
        *(float2*)(ob + (size_t)r0*DIM_ + c) =
            make_float2(tfr(o[ni][0]*inv0), tfr(o[ni][1]*inv0));
        *(float2*)(ob + (size_t)r1*DIM_ + c) =
            make_float2(tfr(o[ni][2]*inv1), tfr(o[ni][3]*inv1));
    }
}

// ---------------- host launch --------------------------------------------------
extern "C" void kernel_launch(void* const* d_in, const int* in_sizes, int n_in,
                              void* d_out, int out_size)
{
    (void)in_sizes; (void)n_in; (void)out_size;
    const float* x_in  = (const float*)d_in[0];
    const float* ctx   = (const float*)d_in[1];
    const float* ln1_g = (const float*)d_in[2];
    const float* ln1_b = (const float*)d_in[3];
    const float* w_qkv = (const float*)d_in[4];
    const float* w_o1  = (const float*)d_in[5];
    const float* b_o1  = (const float*)d_in[6];
    const float* ln2_g = (const float*)d_in[7];
    const float* ln2_b = (const float*)d_in[8];
    const float* w_q   = (const float*)d_in[9];
    const float* w_k   = (const float*)d_in[10];
    const float* w_v   = (const float*)d_in[11];
    const float* w_o2  = (const float*)d_in[12];
    const float* b_o2  = (const float*)d_in[13];
    const float* ln3_g = (const float*)d_in[14];
    const float* ln3_b = (const float*)d_in[15];
    const float* w_ff1 = (const float*)d_in[16];
    const float* b_ff1 = (const float*)d_in[17];
    const float* w_ff2 = (const float*)d_in[18];
    const float* b_ff2 = (const float*)d_in[19];

    float* x = (float*)d_out;

    float *h, *qkv, *q2, *k2, *v2, *o, *mlp, *rctx;
    cudaGetSymbolAddress((void**)&h,    g_h);
    cudaGetSymbolAddress((void**)&qkv,  g_qkv);
    cudaGetSymbolAddress((void**)&q2,   g_q2);
    cudaGetSymbolAddress((void**)&k2,   g_k2);
    cudaGetSymbolAddress((void**)&v2,   g_v2);
    cudaGetSymbolAddress((void**)&o,    g_o);
    cudaGetSymbolAddress((void**)&mlp,  g_mlp);
    cudaGetSymbolAddress((void**)&rctx, g_ctx);

    const int FLASH_SMEM = 3 * 4224 * 4;   // 50688 B
    cudaFuncSetAttribute(flash_k, cudaFuncAttributeMaxDynamicSharedMemorySize,
                         FLASH_SMEM);

    cudaMemcpyAsync(x, x_in, (size_t)ROWS * DIM_ * sizeof(float),
                    cudaMemcpyDeviceToDevice, 0);

    round_k<<<592, 256>>>((const float4*)ctx, (float4*)rctx, ROWS*DIM_/4);

    const dim3 gProj(DIM_/128,  ROWS/128);        // (8,16)
    const dim3 gQKV(3*DIM_/128, ROWS/128);        // (24,16)
    const dim3 gFF1(MLP_/128,   ROWS/128);        // (32,16)
    const dim3 gP3(DIM_/128,    ROWS/128, 3);
    const dim3 gFl(SEQ/64, B_*HEADS_);

    for (int l = 0; l < DEPTH_; l++) {
        const float* wqkv_l = w_qkv + (size_t)l * DIM_ * 3*DIM_;
        const float* wo1_l  = w_o1  + (size_t)l * DIM_ * DIM_;
        const float* wq_l   = w_q   + (size_t)l * DIM_ * DIM_;
        const float* wk_l   = w_k   + (size_t)l * DIM_ * DIM_;
        const float* wv_l   = w_v   + (size_t)l * DIM_ * DIM_;
        const float* wo2_l  = w_o2  + (size_t)l * DIM_ * DIM_;
        const float* wff1_l = w_ff1 + (size_t)l * DIM_ * MLP_;
        const float* wff2_l = w_ff2 + (size_t)l * MLP_ * DIM_;

        // --- self attention ---
        layernorm_k<<<ROWS, 256>>>(x, ln1_g + l*DIM_, ln1_b + l*DIM_, h);
        tcgemm_k<<<gQKV, 256>>>(h, wqkv_l, nullptr, nullptr, qkv,
                                ROWS, 3*DIM_, DIM_, 2);
        flash_k<<<gFl, 256, FLASH_SMEM>>>(qkv, 3*DIM_, qkv + DIM_, 3*DIM_,
                                          qkv + 2*DIM_, 3*DIM_, o);
        tcgemm_k<<<gProj, 256>>>(o, wo1_l, b_o1 + l*DIM_, x, x,
                                 ROWS, DIM_, DIM_, 0);

        // --- cross attention ---
        layernorm_k<<<ROWS, 256>>>(x, ln2_g + l*DIM_, ln2_b + l*DIM_, h);
        tcgemm3_k<<<gP3, 256>>>(h, rctx, rctx,
                                wq_l, wk_l, wv_l,
                                q2, k2, v2);
        flash_k<<<gFl, 256, FLASH_SMEM>>>(q2, DIM_, k2, DIM_, v2, DIM_, o);
        tcgemm_k<<<gProj, 256>>>(o, wo2_l, b_o2 + l*DIM_, x, x,
                                 ROWS, DIM_, DIM_, 0);

        // --- FFN ---
        layernorm_k<<<ROWS, 256>>>(x, ln3_g + l*DIM_, ln3_b + l*DIM_, h);
        tcgemm_k<<<gFF1, 256>>>(h, wff1_l, b_ff1 + l*MLP_, nullptr, mlp,
                                ROWS, MLP_, DIM_, 3);
        tcgemm_k<<<gProj, 256>>>(mlp, wff2_l, b_ff2 + l*DIM_, x, x,
                                 ROWS, DIM_, MLP_, 0);
    }
}

// round 15
// speedup vs baseline: 1.1093x; 1.1093x over previous
#include <cuda_runtime.h>
#include <math.h>
#include <stdint.h>

#define B_      2
#define SEQ     1024
#define DIM_    1024
#define HEADS_  16
#define DH_     64
#define MLP_    4096
#define ROWS    (B_*SEQ)          // 2048
#define SCALE_  0.125f            // 64^-0.5
#define DEPTH_  2

// ---------------- scratch (device globals: allocation-guard-safe) -------------
__device__ float g_h   [ROWS*DIM_];
__device__ float g_qkv [ROWS*3*DIM_];
__device__ float g_q2  [ROWS*DIM_];
__device__ float g_k2  [ROWS*DIM_];
__device__ float g_v2  [ROWS*DIM_];
__device__ float g_o   [ROWS*DIM_];
__device__ float g_mlp [ROWS*MLP_];
__device__ float g_ctx [ROWS*DIM_];   // pre-rounded ctx

// ---------------- helpers ------------------------------------------------------
__device__ __forceinline__ uint32_t f2tf(float f) {
    uint32_t r;
    asm("cvt.rna.tf32.f32 %0, %1;" : "=r"(r) : "f"(f));
    return r;
}
__device__ __forceinline__ float tfr(float f) { return __uint_as_float(f2tf(f)); }
__device__ __forceinline__ uint32_t f2b(float f) { return __float_as_uint(f); }

__device__ __forceinline__ void mma8(float* c, const uint32_t* a, const uint32_t* b) {
    asm volatile(
        "mma.sync.aligned.m16n8k8.row.col.f32.tf32.tf32.f32 "
        "{%0,%1,%2,%3}, {%4,%5,%6,%7}, {%8,%9}, {%0,%1,%2,%3};"
        : "+f"(c[0]), "+f"(c[1]), "+f"(c[2]), "+f"(c[3])
        : "r"(a[0]), "r"(a[1]), "r"(a[2]), "r"(a[3]),
          "r"(b[0]), "r"(b[1]));
}

// A-frag index (M=64, K=64 tile), scalar 33-stride layout (Q and P)
__device__ __forceinline__ int aidx(int row, int k) {
    const int reg = ((k & 7) >> 2) * 2 + ((row & 15) >> 3);
    return (((reg * 8 + (k >> 3)) * 4 + (row >> 4)) * 33) + (row & 7) * 4 + (k & 3);
}
// B-frag index (N=64, K=64 tile), scalar 33-stride layout (K and V)
__device__ __forceinline__ int bidx(int n, int k) {
    const int reg = (k & 4) >> 2;
    return ((((k >> 3) * 2 + reg) * 8 + (n >> 3)) * 33) + (n & 7) * 4 + (k & 3);
}

// ---------------- pre-round pass (ctx only) ------------------------------------
__global__ __launch_bounds__(256) void round_k(
    const float4* __restrict__ in, float4* __restrict__ out, int n4)
{
    const int stride = gridDim.x * blockDim.x;
    for (int i = blockIdx.x*blockDim.x + threadIdx.x; i < n4; i += stride) {
        float4 v = in[i];
        v.x = tfr(v.x); v.y = tfr(v.y); v.z = tfr(v.z); v.w = tfr(v.w);
        out[i] = v;
    }
}

// ---------------- layernorm: one block per row, tf32-rounded output ----------
__global__ __launch_bounds__(256) void layernorm_k(
    const float* __restrict__ x, const float* __restrict__ g,
    const float* __restrict__ b, float* __restrict__ out)
{
    __shared__ float red[18];
    const int row = blockIdx.x;
    const int t   = threadIdx.x;
    const float4 v = ((const float4*)(x + (size_t)row*DIM_))[t];
    float s  = v.x + v.y + v.z + v.w;
    float sq = v.x*v.x + v.y*v.y + v.z*v.z + v.w*v.w;
    #pragma unroll
    for (int o = 16; o > 0; o >>= 1) {
        s  += __shfl_down_sync(0xffffffffu, s,  o);
        sq += __shfl_down_sync(0xffffffffu, sq, o);
    }
    if ((t & 31) == 0) { red[t >> 5] = s; red[8 + (t >> 5)] = sq; }
    __syncthreads();
    if (t < 32) {
        float a = (t < 8) ? red[t]     : 0.f;
        float c = (t < 8) ? red[8 + t] : 0.f;
        #pragma unroll
        for (int o = 4; o > 0; o >>= 1) {
            a += __shfl_down_sync(0xffffffffu, a, o);
            c += __shfl_down_sync(0xffffffffu, c, o);
        }
        if (t == 0) { red[16] = a; red[17] = c; }
    }
    __syncthreads();
    const float mu   = red[16] * (1.f / DIM_);
    const float var  = red[17] * (1.f / DIM_) - mu * mu;
    const float rstd = rsqrtf(var + 1e-5f);
    const float4 gv = ((const float4*)g)[t];
    const float4 bv = ((const float4*)b)[t];
    float4 o4;
    o4.x = tfr((v.x - mu) * rstd * gv.x + bv.x);
    o4.y = tfr((v.y - mu) * rstd * gv.y + bv.y);
    o4.z = tfr((v.z - mu) * rstd * gv.z + bv.z);
    o4.w = tfr((v.w - mu) * rstd * gv.w + bv.w);
    ((float4*)(out + (size_t)row*DIM_))[t] = o4;
}

// ---------------- TF32 GEMM 128x128x32 (round-13 body, unchanged) -------------
__device__ __forceinline__ void gemm_body(
    const float* __restrict__ A, const float* __restrict__ B,
    const float* __restrict__ bias, const float* __restrict__ res,
    float* __restrict__ C, int M, int N, int K, int act,
    int bm, int bn)
{
    __shared__ __align__(16) uint32_t As[4224];
    __shared__ __align__(16) uint32_t Bs[4224];

    const int tid    = threadIdx.x;
    const int lane   = tid & 31;
    const int warp   = tid >> 5;
    const int warp_m = warp >> 2;
    const int warp_n = warp & 3;

    const int ar  = tid >> 3;
    const int aq  = tid & 7;
    const int bkr = tid >> 5;
    const int bq  = tid & 31;

    const float* Abase = A + (size_t)(bm*128)*K;
    const float* Bbase = B + (size_t)(bn*128);

    const int a_j  = aq >> 1;
    const int a_rk = 2*(aq & 1);

    float4 pa[4], pb[4];
    #pragma unroll
    for (int it = 0; it < 4; it++) {
        pa[it] = *(const float4*)(Abase + (size_t)(ar + it*32)*K + aq*4);
        pb[it] = *(const float4*)(Bbase + (size_t)(bkr + it*8)*N + bq*4);
    }

    float acc[4][4][4];
    #pragma unroll
    for (int mi = 0; mi < 4; mi++)
        #pragma unroll
        for (int ni = 0; ni < 4; ni++)
            #pragma unroll
            for (int r = 0; r < 4; r++) acc[mi][ni][r] = 0.f;

    const uint32_t* a_rd = As + lane*4;
    const uint32_t* b_rd = Bs + lane*2;

    for (int kt = 0; kt < K; kt += 32) {
        #pragma unroll
        for (int it = 0; it < 4; it++) {
            {
                const int row = ar + it*32;
                const int i   = row >> 4;
                uint32_t* d = &As[(i*4 + a_j)*132 + (row & 7)*16
                                  + a_rk + ((row & 15) >> 3)];
                d[0]  = f2b(pa[it].x);
                d[4]  = f2b(pa[it].y);
                d[8]  = f2b(pa[it].z);
                d[12] = f2b(pa[it].w);
            }
            {
                const int kb = bkr + it*8;
                uint32_t* e = &Bs[((kb >> 3)*16 + (bq >> 1))*66
                                  + (16*(bq & 1) + (kb & 3))*2 + ((kb & 7) >> 2)];
                e[0]  = f2tf(pb[it].x);
                e[8]  = f2tf(pb[it].y);
                e[16] = f2tf(pb[it].z);
                e[24] = f2tf(pb[it].w);
            }
        }
        __syncthreads();

        if (kt + 32 < K) {
            #pragma unroll
            for (int it = 0; it < 4; it++) {
                pa[it] = *(const float4*)(Abase + (size_t)(ar + it*32)*K + (kt + 32) + aq*4);
                pb[it] = *(const float4*)(Bbase + (size_t)(bkr + it*8 + kt + 32)*N + bq*4);
            }
        }

        #pragma unroll
        for (int j = 0; j < 4; j++) {
            uint4 af[4];
            #pragma unroll
            for (int mi = 0; mi < 4; mi++)
                af[mi] = *(const uint4*)(a_rd + ((warp_m*4 + mi)*4 + j)*132);
            uint2 bf[4];
            #pragma unroll
            for (int ni = 0; ni < 4; ni++)
                bf[ni] = *(const uint2*)(b_rd + (j*16 + warp_n*4 + ni)*66);
            #pragma unroll
            for (int mi = 0; mi < 4; mi++)
                #pragma unroll
                for (int ni = 0; ni < 4; ni++)
                    mma8(acc[mi][ni], (const uint32_t*)&af[mi],
                         (const uint32_t*)&bf[ni]);
        }
        __syncthreads();
    }

    const int r0 = bm*128 + warp_m*64 + (lane >> 2);
    const int c0 = bn*128 + warp_n*32 + 2*(lane & 3);
    #pragma unroll
    for (int mi = 0; mi < 4; mi++) {
        #pragma unroll
        for (int ni = 0; ni < 4; ni++) {
            const int c = c0 + ni*8;
            float2 bv = make_float2(0.f, 0.f);
            if (bias) bv = *(const float2*)&bias[c];
            #pragma unroll
            for (int half = 0; half < 2; half++) {
                const int r = r0 + mi*16 + half*8;
                const size_t idx = (size_t)r * N + c;
                float vx = acc[mi][ni][half*2 + 0] + bv.x;
                float vy = acc[mi][ni][half*2 + 1] + bv.y;
                if (act & 1) { vx = vx * normcdff(vx); vy = vy * normcdff(vy); }
                if (act & 2) { vx = tfr(vx); vy = tfr(vy); }
                if (res) { vx += res[idx]; vy += res[idx + 1]; }
                *(float2*)&C[idx] = make_float2(vx, vy);
            }
        }
    }
}

__global__ __launch_bounds__(256) void tcgemm_k(
    const float* __restrict__ A, const float* __restrict__ B,
    const float* __restrict__ bias, const float* __restrict__ res,
    float* __restrict__ C, int M, int N, int K, int act)
{
    gemm_body(A, B, bias, res, C, M, N, K, act, blockIdx.y, blockIdx.x);
}

__global__ __launch_bounds__(256) void tcgemm3_k(
    const float* __restrict__ A0, const float* __restrict__ A1,
    const float* __restrict__ A2,
    const float* __restrict__ B0, const float* __restrict__ B1,
    const float* __restrict__ B2,
    float* __restrict__ C0, float* __restrict__ C1, float* __restrict__ C2)
{
    const int z = blockIdx.z;
    const float* A = (z == 0) ? A0 : (z == 1) ? A1 : A2;
    const float* B = (z == 0) ? B0 : (z == 1) ? B1 : B2;
    float*       C = (z == 0) ? C0 : (z == 1) ? C1 : C2;
    gemm_body(A, B, nullptr, nullptr, C, ROWS, DIM_, DIM_, 2,
              blockIdx.y, blockIdx.x);
}

// ---------------- fused flash attention: full-row warps -----------------------
// CTA = 128 threads = 4 warps. Warp wm owns Q-rows [wm*16, wm*16+16) x all 64
// KV columns. Softmax is warp-local (quad shuffles); running m/l in registers.
// smem: Qs[4224] | Ks[4224] | Vs[4224] | Ps[4224] (P rows disjoint per warp).
__global__ __launch_bounds__(128) void flash_k(
    const float* __restrict__ Q, int ldq,
    const float* __restrict__ Kp, int ldk,
    const float* __restrict__ V, int ldv,
    float* __restrict__ O)
{
    extern __shared__ uint32_t fsm[];
    uint32_t* Qs = fsm;
    uint32_t* Ks = fsm + 4224;
    uint32_t* Vs = fsm + 8448;
    uint32_t* Ps = fsm + 12672;

    const int bh = blockIdx.y, b = bh >> 4, h = bh & 15;
    const int q0 = blockIdx.x * 64;
    const int tid = threadIdx.x, lane = tid & 31;
    const int wm = tid >> 5;            // 0..3

    // ---- Q fill (pre-rounded input; raw bits; SCALE_ is a power of two) ----
    {
        const float* qb = Q + (size_t)(b*SEQ + q0) * ldq + h*DH_;
        const int r  = tid >> 4;        // 0..7
        const int c4 = (tid & 15) * 4;
        #pragma unroll
        for (int it = 0; it < 8; it++) {
            const int row = r + it*8;
            const float4 v = *(const float4*)(qb + (size_t)row*ldq + c4);
            uint32_t* d = &Qs[aidx(row, c4)];   // 4 consecutive words
            d[0] = f2b(v.x * SCALE_); d[1] = f2b(v.y * SCALE_);
            d[2] = f2b(v.z * SCALE_); d[3] = f2b(v.w * SCALE_);
        }
    }

    float o[8][4];
    #pragma unroll
    for (int ni = 0; ni < 8; ni++)
        #pragma unroll
        for (int c = 0; c < 4; c++) o[ni][c] = 0.f;
    float m0 = -1e30f, m1 = -1e30f, l0 = 0.f, l1 = 0.f;

    const int r0 = wm*16 + (lane >> 2);
    const int r1 = r0 + 8;

    for (int kt = 0; kt < SEQ; kt += 64) {
        __syncthreads();   // protect Ks/Vs from previous tile's readers
        // ---- K/V fill (consecutive-word stores, as in round 13) ----
        {
            const float* kb = Kp + (size_t)(b*SEQ + kt) * ldk + h*DH_;
            const float* vb = V  + (size_t)(b*SEQ + kt) * ldv + h*DH_;
            const int r  = tid >> 4;
            const int c4 = (tid & 15) * 4;
            #pragma unroll
            for (int it = 0; it < 8; it++) {
                const int row = r + it*8;
                const float4 kv4 = *(const float4*)(kb + (size_t)row*ldk + c4);
                uint32_t* d = &Ks[bidx(row, c4)];
                d[0] = f2b(kv4.x); d[1] = f2b(kv4.y);
                d[2] = f2b(kv4.z); d[3] = f2b(kv4.w);
                const float4 vv4 = *(const float4*)(vb + (size_t)row*ldv + c4);
                Vs[bidx(c4+0, row)] = f2b(vv4.x);
                Vs[bidx(c4+1, row)] = f2b(vv4.y);
                Vs[bidx(c4+2, row)] = f2b(vv4.z);
                Vs[bidx(c4+3, row)] = f2b(vv4.w);
            }
        }
        __syncthreads();

        // ---- S = Q K^T : warp covers m16 x n64 x k64 ----
        float s[8][4];
        #pragma unroll
        for (int ni = 0; ni < 8; ni++)
            #pragma unroll
            for (int c = 0; c < 4; c++) s[ni][c] = 0.f;
        #pragma unroll
        for (int j = 0; j < 8; j++) {
            uint32_t af[4];
            #pragma unroll
            for (int r = 0; r < 4; r++)
                af[r] = Qs[((r*8 + j)*4 + wm)*33 + lane];
            #pragma unroll
            for (int ni = 0; ni < 8; ni++) {
                uint32_t bf[2];
                #pragma unroll
                for (int r = 0; r < 2; r++)
                    bf[r] = Ks[((j*2 + r)*8 + ni)*33 + lane];
                mma8(s[ni], af, bf);
            }
        }

        // ---- warp-local online softmax ----
        float mx0 = -1e30f, mx1 = -1e30f;
        #pragma unroll
        for (int ni = 0; ni < 8; ni++) {
            mx0 = fmaxf(mx0, fmaxf(s[ni][0], s[ni][1]));
            mx1 = fmaxf(mx1, fmaxf(s[ni][2], s[ni][3]));
        }
        mx0 = fmaxf(mx0, __shfl_xor_sync(0xffffffffu, mx0, 1));
        mx0 = fmaxf(mx0, __shfl_xor_sync(0xffffffffu, mx0, 2));
        mx1 = fmaxf(mx1, __shfl_xor_sync(0xffffffffu, mx1, 1));
        mx1 = fmaxf(mx1, __shfl_xor_sync(0xffffffffu, mx1, 2));

        const float mn0 = fmaxf(m0, mx0);
        const float mn1 = fmaxf(m1, mx1);
        const float al0 = __expf(m0 - mn0);
        const float al1 = __expf(m1 - mn1);

        float sum0 = 0.f, sum1 = 0.f;
        #pragma unroll
        for (int ni = 0; ni < 8; ni++) {
            const int cb = ni*8 + (lane & 3)*2;
            float p00 = __expf(s[ni][0] - mn0);
            float p01 = __expf(s[ni][1] - mn0);
            float p10 = __expf(s[ni][2] - mn1);
            float p11 = __expf(s[ni][3] - mn1);
            sum0 += p00 + p01;
            sum1 += p10 + p11;
            Ps[aidx(r0, cb    )] = f2tf(p00);
            Ps[aidx(r0, cb + 1)] = f2tf(p01);
            Ps[aidx(r1, cb    )] = f2tf(p10);
            Ps[aidx(r1, cb + 1)] = f2tf(p11);
        }
        sum0 += __shfl_xor_sync(0xffffffffu, sum0, 1);
        sum0 += __shfl_xor_sync(0xffffffffu, sum0, 2);
        sum1 += __shfl_xor_sync(0xffffffffu, sum1, 1);
        sum1 += __shfl_xor_sync(0xffffffffu, sum1, 2);

        m0 = mn0; m1 = mn1;
        l0 = l0*al0 + sum0;
        l1 = l1*al1 + sum1;

        #pragma unroll
        for (int ni = 0; ni < 8; ni++) {
            o[ni][0] *= al0; o[ni][1] *= al0;
            o[ni][2] *= al1; o[ni][3] *= al1;
        }
        __syncwarp();   // P rows are warp-private; order write->read within warp

        // ---- O += P V : warp covers m16 x dh64 x k64(kv) ----
        #pragma unroll
        for (int j = 0; j < 8; j++) {
            uint32_t af[4];
            #pragma unroll
            for (int r = 0; r < 4; r++)
                af[r] = Ps[((r*8 + j)*4 + wm)*33 + lane];
            #pragma unroll
            for (int ni = 0; ni < 8; ni++) {
                uint32_t bf[2];
                #pragma unroll
                for (int r = 0; r < 2; r++)
                    bf[r] = Vs[((j*2 + r)*8 + ni)*33 + lane];
                mma8(o[ni], af, bf);
            }
        }
    }

    // ---- normalize and write merged-head output (rounded for next GEMM) ----
    const float inv0 = 1.f / l0;
    const float inv1 = 1.f / l1;
    float* ob = O + (size_t)(b*SEQ + q0) * DIM_ + h*DH_;
    #pragma unroll
    for (int ni = 0; ni < 8; ni++) {
        const int c = ni*8 + (lane & 3)*2;
        *(float2*)(ob + (size_t)r0*DIM_ + c) =
            make_float2(tfr(o[ni][0]*inv0), tfr(o[ni][1]*inv0));
        *(float2*)(ob + (size_t)r1*DIM_ + c) =
            make_float2(tfr(o[ni][2]*inv1), tfr(o[ni][3]*inv1));
    }
}

// ---------------- host launch --------------------------------------------------
extern "C" void kernel_launch(void* const* d_in, const int* in_sizes, int n_in,
                              void* d_out, int out_size)
{
    (void)in_sizes; (void)n_in; (void)out_size;
    const float* x_in  = (const float*)d_in[0];
    const float* ctx   = (const float*)d_in[1];
    const float* ln1_g = (const float*)d_in[2];
    const float* ln1_b = (const float*)d_in[3];
    const float* w_qkv = (const float*)d_in[4];
    const float* w_o1  = (const float*)d_in[5];
    const float* b_o1  = (const float*)d_in[6];
    const float* ln2_g = (const float*)d_in[7];
    const float* ln2_b = (const float*)d_in[8];
    const float* w_q   = (const float*)d_in[9];
    const float* w_k   = (const float*)d_in[10];
    const float* w_v   = (const float*)d_in[11];
    const float* w_o2  = (const float*)d_in[12];
    const float* b_o2  = (const float*)d_in[13];
    const float* ln3_g = (const float*)d_in[14];
    const float* ln3_b = (const float*)d_in[15];
    const float* w_ff1 = (const float*)d_in[16];
    const float* b_ff1 = (const float*)d_in[17];
    const float* w_ff2 = (const float*)d_in[18];
    const float* b_ff2 = (const float*)d_in[19];

    float* x = (float*)d_out;

    float *h, *qkv, *q2, *k2, *v2, *o, *mlp, *rctx;
    cudaGetSymbolAddress((void**)&h,    g_h);
    cudaGetSymbolAddress((void**)&qkv,  g_qkv);
    cudaGetSymbolAddress((void**)&q2,   g_q2);
    cudaGetSymbolAddress((void**)&k2,   g_k2);
    cudaGetSymbolAddress((void**)&v2,   g_v2);
    cudaGetSymbolAddress((void**)&o,    g_o);
    cudaGetSymbolAddress((void**)&mlp,  g_mlp);
    cudaGetSymbolAddress((void**)&rctx, g_ctx);

    const int FLASH_SMEM = 4 * 4224 * 4;   // 67584 B
    cudaFuncSetAttribute(flash_k, cudaFuncAttributeMaxDynamicSharedMemorySize,
                         FLASH_SMEM);

    cudaMemcpyAsync(x, x_in, (size_t)ROWS * DIM_ * sizeof(float),
                    cudaMemcpyDeviceToDevice, 0);

    round_k<<<592, 256>>>((const float4*)ctx, (float4*)rctx, ROWS*DIM_/4);

    const dim3 gProj(DIM_/128,  ROWS/128);        // (8,16)
    const dim3 gQKV(3*DIM_/128, ROWS/128);        // (24,16)
    const dim3 gFF1(MLP_/128,   ROWS/128);        // (32,16)
    const dim3 gP3(DIM_/128,    ROWS/128, 3);
    const dim3 gFl(SEQ/64, B_*HEADS_);

    for (int l = 0; l < DEPTH_; l++) {
        const float* wqkv_l = w_qkv + (size_t)l * DIM_ * 3*DIM_;
        const float* wo1_l  = w_o1  + (size_t)l * DIM_ * DIM_;
        const float* wq_l   = w_q   + (size_t)l * DIM_ * DIM_;
        const float* wk_l   = w_k   + (size_t)l * DIM_ * DIM_;
        const float* wv_l   = w_v   + (size_t)l * DIM_ * DIM_;
        const float* wo2_l  = w_o2  + (size_t)l * DIM_ * DIM_;
        const float* wff1_l = w_ff1 + (size_t)l * DIM_ * MLP_;
        const float* wff2_l = w_ff2 + (size_t)l * MLP_ * DIM_;

        // --- self attention ---
        layernorm_k<<<ROWS, 256>>>(x, ln1_g + l*DIM_, ln1_b + l*DIM_, h);
        tcgemm_k<<<gQKV, 256>>>(h, wqkv_l, nullptr, nullptr, qkv,
                                ROWS, 3*DIM_, DIM_, 2);
        flash_k<<<gFl, 128, FLASH_SMEM>>>(qkv, 3*DIM_, qkv + DIM_, 3*DIM_,
                                          qkv + 2*DIM_, 3*DIM_, o);
        tcgemm_k<<<gProj, 256>>>(o, wo1_l, b_o1 + l*DIM_, x, x,
                                 ROWS, DIM_, DIM_, 0);

        // --- cross attention ---
        layernorm_k<<<ROWS, 256>>>(x, ln2_g + l*DIM_, ln2_b + l*DIM_, h);
        tcgemm3_k<<<gP3, 256>>>(h, rctx, rctx,
                                wq_l, wk_l, wv_l,
                                q2, k2, v2);
        flash_k<<<gFl, 128, FLASH_SMEM>>>(q2, DIM_, k2, DIM_, v2, DIM_, o);
        tcgemm_k<<<gProj, 256>>>(o, wo2_l, b_o2 + l*DIM_, x, x,
                                 ROWS, DIM_, DIM_, 0);

        // --- FFN ---
        layernorm_k<<<ROWS, 256>>>(x, ln3_g + l*DIM_, ln3_b + l*DIM_, h);
        tcgemm_k<<<gFF1, 256>>>(h, wff1_l, b_ff1 + l*MLP_, nullptr, mlp,
                                ROWS, MLP_, DIM_, 3);
        tcgemm_k<<<gProj, 256>>>(mlp, wff2_l, b_ff2 + l*DIM_, x, x,
                                 ROWS, DIM_, MLP_, 0);
    }
}

// round 16
// speedup vs baseline: 1.1894x; 1.0721x over previous
#include <cuda_runtime.h>
#include <math.h>
#include <stdint.h>

#define B_      2
#define SEQ     1024
#define DIM_    1024
#define HEADS_  16
#define DH_     64
#define MLP_    4096
#define ROWS    (B_*SEQ)          // 2048
#define SCALE_  0.125f            // 64^-0.5
#define DEPTH_  2

// ---------------- scratch (device globals: allocation-guard-safe) -------------
__device__ float g_h   [ROWS*DIM_];
__device__ float g_qkv [ROWS*3*DIM_];
__device__ float g_q2  [ROWS*DIM_];
__device__ float g_k2  [ROWS*DIM_];
__device__ float g_v2  [ROWS*DIM_];
__device__ float g_o   [ROWS*DIM_];
__device__ float g_mlp [ROWS*MLP_];
__device__ float g_ctx [ROWS*DIM_];   // pre-rounded ctx

// ---------------- helpers ------------------------------------------------------
__device__ __forceinline__ uint32_t f2tf(float f) {
    uint32_t r;
    asm("cvt.rna.tf32.f32 %0, %1;" : "=r"(r) : "f"(f));
    return r;
}
__device__ __forceinline__ float tfr(float f) { return __uint_as_float(f2tf(f)); }
__device__ __forceinline__ uint32_t f2b(float f) { return __float_as_uint(f); }

__device__ __forceinline__ void mma8(float* c, const uint32_t* a, const uint32_t* b) {
    asm volatile(
        "mma.sync.aligned.m16n8k8.row.col.f32.tf32.tf32.f32 "
        "{%0,%1,%2,%3}, {%4,%5,%6,%7}, {%8,%9}, {%0,%1,%2,%3};"
        : "+f"(c[0]), "+f"(c[1]), "+f"(c[2]), "+f"(c[3])
        : "r"(a[0]), "r"(a[1]), "r"(a[2]), "r"(a[3]),
          "r"(b[0]), "r"(b[1]));
}

// A-frag index, M=128 x K=64 tile (flash Q and P): i = row>>4 in 0..7
__device__ __forceinline__ int aidx128(int row, int k) {
    const int reg = ((k & 7) >> 2) * 2 + ((row & 15) >> 3);
    return (((reg * 8 + (k >> 3)) * 8 + (row >> 4)) * 33) + (row & 7) * 4 + (k & 3);
}
// B-frag index, N=64 x K=64 tile (flash K and V)
__device__ __forceinline__ int bidx(int n, int k) {
    const int reg = (k & 4) >> 2;
    return ((((k >> 3) * 2 + reg) * 8 + (n >> 3)) * 33) + (n & 7) * 4 + (k & 3);
}

// ---------------- pre-round pass (ctx only) ------------------------------------
__global__ __launch_bounds__(256) void round_k(
    const float4* __restrict__ in, float4* __restrict__ out, int n4)
{
    const int stride = gridDim.x * blockDim.x;
    for (int i = blockIdx.x*blockDim.x + threadIdx.x; i < n4; i += stride) {
        float4 v = in[i];
        v.x = tfr(v.x); v.y = tfr(v.y); v.z = tfr(v.z); v.w = tfr(v.w);
        out[i] = v;
    }
}

// ---------------- layernorm: one block per row, tf32-rounded output ----------
__global__ __launch_bounds__(256) void layernorm_k(
    const float* __restrict__ x, const float* __restrict__ g,
    const float* __restrict__ b, float* __restrict__ out)
{
    __shared__ float red[18];
    const int row = blockIdx.x;
    const int t   = threadIdx.x;
    const float4 v = ((const float4*)(x + (size_t)row*DIM_))[t];
    float s  = v.x + v.y + v.z + v.w;
    float sq = v.x*v.x + v.y*v.y + v.z*v.z + v.w*v.w;
    #pragma unroll
    for (int o = 16; o > 0; o >>= 1) {
        s  += __shfl_down_sync(0xffffffffu, s,  o);
        sq += __shfl_down_sync(0xffffffffu, sq, o);
    }
    if ((t & 31) == 0) { red[t >> 5] = s; red[8 + (t >> 5)] = sq; }
    __syncthreads();
    if (t < 32) {
        float a = (t < 8) ? red[t]     : 0.f;
        float c = (t < 8) ? red[8 + t] : 0.f;
        #pragma unroll
        for (int o = 4; o > 0; o >>= 1) {
            a += __shfl_down_sync(0xffffffffu, a, o);
            c += __shfl_down_sync(0xffffffffu, c, o);
        }
        if (t == 0) { red[16] = a; red[17] = c; }
    }
    __syncthreads();
    const float mu   = red[16] * (1.f / DIM_);
    const float var  = red[17] * (1.f / DIM_) - mu * mu;
    const float rstd = rsqrtf(var + 1e-5f);
    const float4 gv = ((const float4*)g)[t];
    const float4 bv = ((const float4*)b)[t];
    float4 o4;
    o4.x = tfr((v.x - mu) * rstd * gv.x + bv.x);
    o4.y = tfr((v.y - mu) * rstd * gv.y + bv.y);
    o4.z = tfr((v.z - mu) * rstd * gv.z + bv.z);
    o4.w = tfr((v.w - mu) * rstd * gv.w + bv.w);
    ((float4*)(out + (size_t)row*DIM_))[t] = o4;
}

// ---------------- TF32 GEMM 128x128x32 (round-13 body, unchanged) -------------
__device__ __forceinline__ void gemm_body(
    const float* __restrict__ A, const float* __restrict__ B,
    const float* __restrict__ bias, const float* __restrict__ res,
    float* __restrict__ C, int M, int N, int K, int act,
    int bm, int bn)
{
    __shared__ __align__(16) uint32_t As[4224];
    __shared__ __align__(16) uint32_t Bs[4224];

    const int tid    = threadIdx.x;
    const int lane   = tid & 31;
    const int warp   = tid >> 5;
    const int warp_m = warp >> 2;
    const int warp_n = warp & 3;

    const int ar  = tid >> 3;
    const int aq  = tid & 7;
    const int bkr = tid >> 5;
    const int bq  = tid & 31;

    const float* Abase = A + (size_t)(bm*128)*K;
    const float* Bbase = B + (size_t)(bn*128);

    const int a_j  = aq >> 1;
    const int a_rk = 2*(aq & 1);

    float4 pa[4], pb[4];
    #pragma unroll
    for (int it = 0; it < 4; it++) {
        pa[it] = *(const float4*)(Abase + (size_t)(ar + it*32)*K + aq*4);
        pb[it] = *(const float4*)(Bbase + (size_t)(bkr + it*8)*N + bq*4);
    }

    float acc[4][4][4];
    #pragma unroll
    for (int mi = 0; mi < 4; mi++)
        #pragma unroll
        for (int ni = 0; ni < 4; ni++)
            #pragma unroll
            for (int r = 0; r < 4; r++) acc[mi][ni][r] = 0.f;

    const uint32_t* a_rd = As + lane*4;
    const uint32_t* b_rd = Bs + lane*2;

    for (int kt = 0; kt < K; kt += 32) {
        #pragma unroll
        for (int it = 0; it < 4; it++) {
            {
                const int row = ar + it*32;
                const int i   = row >> 4;
                uint32_t* d = &As[(i*4 + a_j)*132 + (row & 7)*16
                                  + a_rk + ((row & 15) >> 3)];
                d[0]  = f2b(pa[it].x);
                d[4]  = f2b(pa[it].y);
                d[8]  = f2b(pa[it].z);
                d[12] = f2b(pa[it].w);
            }
            {
                const int kb = bkr + it*8;
                uint32_t* e = &Bs[((kb >> 3)*16 + (bq >> 1))*66
                                  + (16*(bq & 1) + (kb & 3))*2 + ((kb & 7) >> 2)];
                e[0]  = f2tf(pb[it].x);
                e[8]  = f2tf(pb[it].y);
                e[16] = f2tf(pb[it].z);
                e[24] = f2tf(pb[it].w);
            }
        }
        __syncthreads();

        if (kt + 32 < K) {
            #pragma unroll
            for (int it = 0; it < 4; it++) {
                pa[it] = *(const float4*)(Abase + (size_t)(ar + it*32)*K + (kt + 32) + aq*4);
                pb[it] = *(const float4*)(Bbase + (size_t)(bkr + it*8 + kt + 32)*N + bq*4);
            }
        }

        #pragma unroll
        for (int j = 0; j < 4; j++) {
            uint4 af[4];
            #pragma unroll
            for (int mi = 0; mi < 4; mi++)
                af[mi] = *(const uint4*)(a_rd + ((warp_m*4 + mi)*4 + j)*132);
            uint2 bf[4];
            #pragma unroll
            for (int ni = 0; ni < 4; ni++)
                bf[ni] = *(const uint2*)(b_rd + (j*16 + warp_n*4 + ni)*66);
            #pragma unroll
            for (int mi = 0; mi < 4; mi++)
                #pragma unroll
                for (int ni = 0; ni < 4; ni++)
                    mma8(acc[mi][ni], (const uint32_t*)&af[mi],
                         (const uint32_t*)&bf[ni]);
        }
        __syncthreads();
    }

    const int r0 = bm*128 + warp_m*64 + (lane >> 2);
    const int c0 = bn*128 + warp_n*32 + 2*(lane & 3);
    #pragma unroll
    for (int mi = 0; mi < 4; mi++) {
        #pragma unroll
        for (int ni = 0; ni < 4; ni++) {
            const int c = c0 + ni*8;
            float2 bv = make_float2(0.f, 0.f);
            if (bias) bv = *(const float2*)&bias[c];
            #pragma unroll
            for (int half = 0; half < 2; half++) {
                const int r = r0 + mi*16 + half*8;
                const size_t idx = (size_t)r * N + c;
                float vx = acc[mi][ni][half*2 + 0] + bv.x;
                float vy = acc[mi][ni][half*2 + 1] + bv.y;
                if (act & 1) { vx = vx * normcdff(vx); vy = vy * normcdff(vy); }
                if (act & 2) { vx = tfr(vx); vy = tfr(vy); }
                if (res) { vx += res[idx]; vy += res[idx + 1]; }
                *(float2*)&C[idx] = make_float2(vx, vy);
            }
        }
    }
}

__global__ __launch_bounds__(256) void tcgemm_k(
    const float* __restrict__ A, const float* __restrict__ B,
    const float* __restrict__ bias, const float* __restrict__ res,
    float* __restrict__ C, int M, int N, int K, int act)
{
    gemm_body(A, B, bias, res, C, M, N, K, act, blockIdx.y, blockIdx.x);
}

__global__ __launch_bounds__(256) void tcgemm3_k(
    const float* __restrict__ A0, const float* __restrict__ A1,
    const float* __restrict__ A2,
    const float* __restrict__ B0, const float* __restrict__ B1,
    const float* __restrict__ B2,
    float* __restrict__ C0, float* __restrict__ C1, float* __restrict__ C2)
{
    const int z = blockIdx.z;
    const float* A = (z == 0) ? A0 : (z == 1) ? A1 : A2;
    const float* B = (z == 0) ? B0 : (z == 1) ? B1 : B2;
    float*       C = (z == 0) ? C0 : (z == 1) ? C1 : C2;
    gemm_body(A, B, nullptr, nullptr, C, ROWS, DIM_, DIM_, 2,
              blockIdx.y, blockIdx.x);
}

// ---------------- fused flash attention: m32 warp tiles, 128-row Q ------------
// CTA = 128 threads = 4 warps. Warp wm owns Q-rows [wm*32, wm*32+32) x all 64
// KV cols (i = 2wm, 2wm+1). Warp-local softmax; running m/l in registers.
// smem: Qs[8448] | Ks[4224] | Vs[4224] | Ps[8448]  (25344 words = 99 KB)
__global__ __launch_bounds__(128) void flash_k(
    const float* __restrict__ Q, int ldq,
    const float* __restrict__ Kp, int ldk,
    const float* __restrict__ V, int ldv,
    float* __restrict__ O)
{
    extern __shared__ uint32_t fsm[];
    uint32_t* Qs = fsm;
    uint32_t* Ks = fsm + 8448;
    uint32_t* Vs = fsm + 12672;
    uint32_t* Ps = fsm + 16896;

    const int bh = blockIdx.y, b = bh >> 4, h = bh & 15;
    const int q0 = blockIdx.x * 128;
    const int tid = threadIdx.x, lane = tid & 31;
    const int wm = tid >> 5;            // 0..3

    // ---- Q fill: 128 rows x 64 cols (pre-rounded; raw bits) ----
    {
        const float* qb = Q + (size_t)(b*SEQ + q0) * ldq + h*DH_;
        const int r  = tid >> 4;        // 0..7
        const int c4 = (tid & 15) * 4;
        #pragma unroll
        for (int it = 0; it < 16; it++) {
            const int row = r + it*8;
            const float4 v = *(const float4*)(qb + (size_t)row*ldq + c4);
            uint32_t* d = &Qs[aidx128(row, c4)];   // 4 consecutive words
            d[0] = f2b(v.x * SCALE_); d[1] = f2b(v.y * SCALE_);
            d[2] = f2b(v.z * SCALE_); d[3] = f2b(v.w * SCALE_);
        }
    }

    float o[2][8][4];
    #pragma unroll
    for (int mi = 0; mi < 2; mi++)
        #pragma unroll
        for (int ni = 0; ni < 8; ni++)
            #pragma unroll
            for (int c = 0; c < 4; c++) o[mi][ni][c] = 0.f;
    float mrow[4] = {-1e30f, -1e30f, -1e30f, -1e30f};
    float lrow[4] = {0.f, 0.f, 0.f, 0.f};

    const int r0 = wm*32 + (lane >> 2);   // thread's base row (mi=0, half=0)

    for (int kt = 0; kt < SEQ; kt += 64) {
        __syncthreads();
        // ---- K/V fill (64 x 64 tile; consecutive-word K stores) ----
        {
            const float* kb = Kp + (size_t)(b*SEQ + kt) * ldk + h*DH_;
            const float* vb = V  + (size_t)(b*SEQ + kt) * ldv + h*DH_;
            const int r  = tid >> 4;
            const int c4 = (tid & 15) * 4;
            #pragma unroll
            for (int it = 0; it < 8; it++) {
                const int row = r + it*8;
                const float4 kv4 = *(const float4*)(kb + (size_t)row*ldk + c4);
                uint32_t* d = &Ks[bidx(row, c4)];
                d[0] = f2b(kv4.x); d[1] = f2b(kv4.y);
                d[2] = f2b(kv4.z); d[3] = f2b(kv4.w);
                const float4 vv4 = *(const float4*)(vb + (size_t)row*ldv + c4);
                Vs[bidx(c4+0, row)] = f2b(vv4.x);
                Vs[bidx(c4+1, row)] = f2b(vv4.y);
                Vs[bidx(c4+2, row)] = f2b(vv4.z);
                Vs[bidx(c4+3, row)] = f2b(vv4.w);
            }
        }
        __syncthreads();

        // ---- S = Q K^T : warp covers m32 x n64 x k64 ----
        float s[2][8][4];
        #pragma unroll
        for (int mi = 0; mi < 2; mi++)
            #pragma unroll
            for (int ni = 0; ni < 8; ni++)
                #pragma unroll
                for (int c = 0; c < 4; c++) s[mi][ni][c] = 0.f;
        #pragma unroll
        for (int j = 0; j < 8; j++) {
            uint32_t af[2][4];
            #pragma unroll
            for (int mi = 0; mi < 2; mi++)
                #pragma unroll
                for (int r = 0; r < 4; r++)
                    af[mi][r] = Qs[((r*8 + j)*8 + wm*2 + mi)*33 + lane];
            #pragma unroll
            for (int ni = 0; ni < 8; ni++) {
                uint32_t bf[2];
                #pragma unroll
                for (int r = 0; r < 2; r++)
                    bf[r] = Ks[((j*2 + r)*8 + ni)*33 + lane];
                mma8(s[0][ni], af[0], bf);
                mma8(s[1][ni], af[1], bf);
            }
        }

        // ---- warp-local online softmax (4 rows per thread) ----
        #pragma unroll
        for (int mi = 0; mi < 2; mi++) {
            float mx0 = -1e30f, mx1 = -1e30f;
            #pragma unroll
            for (int ni = 0; ni < 8; ni++) {
                mx0 = fmaxf(mx0, fmaxf(s[mi][ni][0], s[mi][ni][1]));
                mx1 = fmaxf(mx1, fmaxf(s[mi][ni][2], s[mi][ni][3]));
            }
            mx0 = fmaxf(mx0, __shfl_xor_sync(0xffffffffu, mx0, 1));
            mx0 = fmaxf(mx0, __shfl_xor_sync(0xffffffffu, mx0, 2));
            mx1 = fmaxf(mx1, __shfl_xor_sync(0xffffffffu, mx1, 1));
            mx1 = fmaxf(mx1, __shfl_xor_sync(0xffffffffu, mx1, 2));

            const float mn0 = fmaxf(mrow[mi*2    ], mx0);
            const float mn1 = fmaxf(mrow[mi*2 + 1], mx1);
            const float al0 = __expf(mrow[mi*2    ] - mn0);
            const float al1 = __expf(mrow[mi*2 + 1] - mn1);

            const int rr0 = r0 + mi*16;
            const int rr1 = rr0 + 8;
            float sum0 = 0.f, sum1 = 0.f;
            #pragma unroll
            for (int ni = 0; ni < 8; ni++) {
                const int cb = ni*8 + (lane & 3)*2;
                float p00 = __expf(s[mi][ni][0] - mn0);
                float p01 = __expf(s[mi][ni][1] - mn0);
                float p10 = __expf(s[mi][ni][2] - mn1);
                float p11 = __expf(s[mi][ni][3] - mn1);
                sum0 += p00 + p01;
                sum1 += p10 + p11;
                Ps[aidx128(rr0, cb    )] = f2tf(p00);
                Ps[aidx128(rr0, cb + 1)] = f2tf(p01);
                Ps[aidx128(rr1, cb    )] = f2tf(p10);
                Ps[aidx128(rr1, cb + 1)] = f2tf(p11);
            }
            sum0 += __shfl_xor_sync(0xffffffffu, sum0, 1);
            sum0 += __shfl_xor_sync(0xffffffffu, sum0, 2);
            sum1 += __shfl_xor_sync(0xffffffffu, sum1, 1);
            sum1 += __shfl_xor_sync(0xffffffffu, sum1, 2);

            mrow[mi*2    ] = mn0;
            mrow[mi*2 + 1] = mn1;
            lrow[mi*2    ] = lrow[mi*2    ]*al0 + sum0;
            lrow[mi*2 + 1] = lrow[mi*2 + 1]*al1 + sum1;

            #pragma unroll
            for (int ni = 0; ni < 8; ni++) {
                o[mi][ni][0] *= al0; o[mi][ni][1] *= al0;
                o[mi][ni][2] *= al1; o[mi][ni][3] *= al1;
            }
        }
        __syncwarp();   // P rows warp-private: order writes->reads within warp

        // ---- O += P V : warp covers m32 x dh64 x k64(kv) ----
        #pragma unroll
        for (int j = 0; j < 8; j++) {
            uint32_t af[2][4];
            #pragma unroll
            for (int mi = 0; mi < 2; mi++)
                #pragma unroll
                for (int r = 0; r < 4; r++)
                    af[mi][r] = Ps[((r*8 + j)*8 + wm*2 + mi)*33 + lane];
            #pragma unroll
            for (int ni = 0; ni < 8; ni++) {
                uint32_t bf[2];
                #pragma unroll
                for (int r = 0; r < 2; r++)
                    bf[r] = Vs[((j*2 + r)*8 + ni)*33 + lane];
                mma8(o[0][ni], af[0], bf);
                mma8(o[1][ni], af[1], bf);
            }
        }
    }

    // ---- normalize and write merged-head output (rounded for next GEMM) ----
    float* ob = O + (size_t)(b*SEQ + q0) * DIM_ + h*DH_;
    #pragma unroll
    for (int mi = 0; mi < 2; mi++) {
        const float inv0 = 1.f / lrow[mi*2];
        const float inv1 = 1.f / lrow[mi*2 + 1];
        const int rr0 = r0 + mi*16;
        const int rr1 = rr0 + 8;
        #pragma unroll
        for (int ni = 0; ni < 8; ni++) {
            const int c = ni*8 + (lane & 3)*2;
            *(float2*)(ob + (size_t)rr0*DIM_ + c) =
                make_float2(tfr(o[mi][ni][0]*inv0), tfr(o[mi][ni][1]*inv0));
            *(float2*)(ob + (size_t)rr1*DIM_ + c) =
                make_float2(tfr(o[mi][ni][2]*inv1), tfr(o[mi][ni][3]*inv1));
        }
    }
}

// ---------------- host launch --------------------------------------------------
extern "C" void kernel_launch(void* const* d_in, const int* in_sizes, int n_in,
                              void* d_out, int out_size)
{
    (void)in_sizes; (void)n_in; (void)out_size;
    const float* x_in  = (const float*)d_in[0];
    const float* ctx   = (const float*)d_in[1];
    const float* ln1_g = (const float*)d_in[2];
    const float* ln1_b = (const float*)d_in[3];
    const float* w_qkv = (const float*)d_in[4];
    const float* w_o1  = (const float*)d_in[5];
    const float* b_o1  = (const float*)d_in[6];
    const float* ln2_g = (const float*)d_in[7];
    const float* ln2_b = (const float*)d_in[8];
    const float* w_q   = (const float*)d_in[9];
    const float* w_k   = (const float*)d_in[10];
    const float* w_v   = (const float*)d_in[11];
    const float* w_o2  = (const float*)d_in[12];
    const float* b_o2  = (const float*)d_in[13];
    const float* ln3_g = (const float*)d_in[14];
    const float* ln3_b = (const float*)d_in[15];
    const float* w_ff1 = (const float*)d_in[16];
    const float* b_ff1 = (const float*)d_in[17];
    const float* w_ff2 = (const float*)d_in[18];
    const float* b_ff2 = (const float*)d_in[19];

    float* x = (float*)d_out;

    float *h, *qkv, *q2, *k2, *v2, *o, *mlp, *rctx;
    cudaGetSymbolAddress((void**)&h,    g_h);
    cudaGetSymbolAddress((void**)&qkv,  g_qkv);
    cudaGetSymbolAddress((void**)&q2,   g_q2);
    cudaGetSymbolAddress((void**)&k2,   g_k2);
    cudaGetSymbolAddress((void**)&v2,   g_v2);
    cudaGetSymbolAddress((void**)&o,    g_o);
    cudaGetSymbolAddress((void**)&mlp,  g_mlp);
    cudaGetSymbolAddress((void**)&rctx, g_ctx);

    const int FLASH_SMEM = 25344 * 4;   // 101376 B
    cudaFuncSetAttribute(flash_k, cudaFuncAttributeMaxDynamicSharedMemorySize,
                         FLASH_SMEM);

    cudaMemcpyAsync(x, x_in, (size_t)ROWS * DIM_ * sizeof(float),
                    cudaMemcpyDeviceToDevice, 0);

    round_k<<<592, 256>>>((const float4*)ctx, (float4*)rctx, ROWS*DIM_/4);

    const dim3 gProj(DIM_/128,  ROWS/128);        // (8,16)
    const dim3 gQKV(3*DIM_/128, ROWS/128);        // (24,16)
    const dim3 gFF1(MLP_/128,   ROWS/128);        // (32,16)
    const dim3 gP3(DIM_/128,    ROWS/128, 3);
    const dim3 gFl(SEQ/128, B_*HEADS_);           // (8,32) = 256 CTAs

    for (int l = 0; l < DEPTH_; l++) {
        const float* wqkv_l = w_qkv + (size_t)l * DIM_ * 3*DIM_;
        const float* wo1_l  = w_o1  + (size_t)l * DIM_ * DIM_;
        const float* wq_l   = w_q   + (size_t)l * DIM_ * DIM_;
        const float* wk_l   = w_k   + (size_t)l * DIM_ * DIM_;
        const float* wv_l   = w_v   + (size_t)l * DIM_ * DIM_;
        const float* wo2_l  = w_o2  + (size_t)l * DIM_ * DIM_;
        const float* wff1_l = w_ff1 + (size_t)l * DIM_ * MLP_;
        const float* wff2_l = w_ff2 + (size_t)l * MLP_ * DIM_;

        // --- self attention ---
        layernorm_k<<<ROWS, 256>>>(x, ln1_g + l*DIM_, ln1_b + l*DIM_, h);
        tcgemm_k<<<gQKV, 256>>>(h, wqkv_l, nullptr, nullptr, qkv,
                                ROWS, 3*DIM_, DIM_, 2);
        flash_k<<<gFl, 128, FLASH_SMEM>>>(qkv, 3*DIM_, qkv + DIM_, 3*DIM_,
                                          qkv + 2*DIM_, 3*DIM_, o);
        tcgemm_k<<<gProj, 256>>>(o, wo1_l, b_o1 + l*DIM_, x, x,
                                 ROWS, DIM_, DIM_, 0);

        // --- cross attention ---
        layernorm_k<<<ROWS, 256>>>(x, ln2_g + l*DIM_, ln2_b + l*DIM_, h);
        tcgemm3_k<<<gP3, 256>>>(h, rctx, rctx,
                                wq_l, wk_l, wv_l,
                                q2, k2, v2);
        flash_k<<<gFl, 128, FLASH_SMEM>>>(q2, DIM_, k2, DIM_, v2, DIM_, o);
        tcgemm_k<<<gProj, 256>>>(o, wo2_l, b_o2 + l*DIM_, x, x,
                                 ROWS, DIM_, DIM_, 0);

        // --- FFN ---
        layernorm_k<<<ROWS, 256>>>(x, ln3_g + l*DIM_, ln3_b + l*DIM_, h);
        tcgemm_k<<<gFF1, 256>>>(h, wff1_l, b_ff1 + l*MLP_, nullptr, mlp,
                                ROWS, MLP_, DIM_, 3);
        tcgemm_k<<<gProj, 256>>>(mlp, wff2_l, b_ff2 + l*DIM_, x, x,
                                 ROWS, DIM_, MLP_, 0);
    }
}